// round 7
// baseline (speedup 1.0000x reference)
#include <cuda_runtime.h>

#define N_NODES 100000
#define IN_DIM 500
#define HID 32
#define HEADS 4
#define F1 128            // HEADS*HID
#define OUT_DIM 3
#define NEG 0.2f

// ---------------- scratch (device globals; no allocation allowed) ----------
__device__ float g_z1[N_NODES * F1];
__device__ float g_el1[N_NODES * HEADS];
__device__ float g_er1[N_NODES * HEADS];
__device__ float g_h[N_NODES * F1];
__device__ float g_z2[N_NODES * OUT_DIM];
__device__ float g_el2[N_NODES];
__device__ float g_er2[N_NODES];
__device__ int   g_row[N_NODES + 1];

// ---------------- CSR row offsets from sorted dst --------------------------
__global__ void build_offsets(const int* __restrict__ dst, int E) {
    int i = blockIdx.x * blockDim.x + threadIdx.x;
    if (i >= E) return;
    int d = dst[i];
    if (i == 0) {
        for (int n = 0; n <= d; n++) g_row[n] = 0;
    } else {
        int pd = dst[i - 1];
        for (int n = pd + 1; n <= d; n++) g_row[n] = i;
    }
    if (i == E - 1) {
        for (int n = d + 1; n <= N_NODES; n++) g_row[n] = E;
    }
}

// ---------------- GEMM1: z1 = X[100000,500] @ W1[500,128] ------------------
// 128x128 block tile, BK=16, 256 threads, 8x8 per thread.
// Double-buffered smem with register-staged prefetch.
// Epilogue also computes el1/er1 (fused attention logits).
__global__ void __launch_bounds__(256) gemm1_kernel(const float* __restrict__ X,
                                                    const float* __restrict__ W,
                                                    const float* __restrict__ al,
                                                    const float* __restrict__ ar) {
    __shared__ float As[2][16][128];   // [buf][k][m]
    __shared__ float Bs[2][16][128];   // [buf][k][n]
    int tid = threadIdx.x;
    int m0 = blockIdx.x * 128;
    int tx = tid & 15;       // 16 col-groups of 8
    int ty = tid >> 4;       // 16 row-groups of 8
    float acc[8][8];
#pragma unroll
    for (int i = 0; i < 8; i++)
#pragma unroll
        for (int j = 0; j < 8; j++) acc[i][j] = 0.f;

    const int NF4 = IN_DIM / 4;  // 125 float4 per X row

    int a_ml[2], a_c4[2], b_kl[2], b_n4[2];
#pragma unroll
    for (int p = 0; p < 2; p++) {
        int idx = tid + p * 256;
        a_ml[p] = idx >> 2; a_c4[p] = idx & 3;
        b_kl[p] = idx >> 5; b_n4[p] = idx & 31;
    }

    auto loadA = [&](int k0, int p) -> float4 {
        int gk4 = (k0 >> 2) + a_c4[p];
        int gm = m0 + a_ml[p];
        if (gm < N_NODES && gk4 < NF4)
            return *reinterpret_cast<const float4*>(&X[(long)gm * IN_DIM + gk4 * 4]);
        return make_float4(0.f, 0.f, 0.f, 0.f);
    };
    auto loadB = [&](int k0, int p) -> float4 {
        int gk = k0 + b_kl[p];
        if (gk < IN_DIM)
            return *reinterpret_cast<const float4*>(&W[gk * F1 + b_n4[p] * 4]);
        return make_float4(0.f, 0.f, 0.f, 0.f);
    };
    auto storeA = [&](int buf, int p, float4 v) {
        As[buf][a_c4[p] * 4 + 0][a_ml[p]] = v.x;
        As[buf][a_c4[p] * 4 + 1][a_ml[p]] = v.y;
        As[buf][a_c4[p] * 4 + 2][a_ml[p]] = v.z;
        As[buf][a_c4[p] * 4 + 3][a_ml[p]] = v.w;
    };
    auto storeB = [&](int buf, int p, float4 v) {
        *reinterpret_cast<float4*>(&Bs[buf][b_kl[p]][b_n4[p] * 4]) = v;
    };

    // Prologue: fill buffer 0 with tile k0=0
    {
        float4 ra0 = loadA(0, 0), ra1 = loadA(0, 1);
        float4 rb0 = loadB(0, 0), rb1 = loadB(0, 1);
        storeA(0, 0, ra0); storeA(0, 1, ra1);
        storeB(0, 0, rb0); storeB(0, 1, rb1);
    }
    __syncthreads();

    const int NTILES = (IN_DIM + 15) / 16;  // 32 (last partial: k0=496)
    int buf = 0;
    for (int t = 0; t < NTILES; t++) {
        float4 ra0, ra1, rb0, rb1;
        bool has_next = (t + 1 < NTILES);
        if (has_next) {
            int k0n = (t + 1) * 16;
            ra0 = loadA(k0n, 0); ra1 = loadA(k0n, 1);
            rb0 = loadB(k0n, 0); rb1 = loadB(k0n, 1);
        }
#pragma unroll
        for (int kk = 0; kk < 16; kk++) {
            float a[8], b[8];
#pragma unroll
            for (int i = 0; i < 8; i += 4) {
                float4 v = *reinterpret_cast<const float4*>(&As[buf][kk][ty * 8 + i]);
                a[i] = v.x; a[i + 1] = v.y; a[i + 2] = v.z; a[i + 3] = v.w;
            }
#pragma unroll
            for (int j = 0; j < 8; j += 4) {
                float4 v = *reinterpret_cast<const float4*>(&Bs[buf][kk][tx * 8 + j]);
                b[j] = v.x; b[j + 1] = v.y; b[j + 2] = v.z; b[j + 3] = v.w;
            }
#pragma unroll
            for (int i = 0; i < 8; i++)
#pragma unroll
                for (int j = 0; j < 8; j++) acc[i][j] += a[i] * b[j];
        }
        if (has_next) {
            int nb = buf ^ 1;
            storeA(nb, 0, ra0); storeA(nb, 1, ra1);
            storeB(nb, 0, rb0); storeB(nb, 1, rb1);
            __syncthreads();
            buf = nb;
        }
    }

    // --- epilogue: store z1 and fused el1/er1 ---
    float av[8], rv[8];
#pragma unroll
    for (int j = 0; j < 8; j += 4) {
        float4 v = *reinterpret_cast<const float4*>(&al[tx * 8 + j]);
        av[j] = v.x; av[j + 1] = v.y; av[j + 2] = v.z; av[j + 3] = v.w;
        v = *reinterpret_cast<const float4*>(&ar[tx * 8 + j]);
        rv[j] = v.x; rv[j + 1] = v.y; rv[j + 2] = v.z; rv[j + 3] = v.w;
    }
    int head = tx >> 2;
#pragma unroll
    for (int i = 0; i < 8; i++) {
        int gm = m0 + ty * 8 + i;
        float pl = 0.f, pr = 0.f;
#pragma unroll
        for (int j = 0; j < 8; j++) {
            pl += acc[i][j] * av[j];
            pr += acc[i][j] * rv[j];
        }
        pl += __shfl_xor_sync(0xffffffffu, pl, 1);
        pr += __shfl_xor_sync(0xffffffffu, pr, 1);
        pl += __shfl_xor_sync(0xffffffffu, pl, 2);
        pr += __shfl_xor_sync(0xffffffffu, pr, 2);
        if (gm < N_NODES) {
            if ((tx & 3) == 0) {
                g_el1[gm * HEADS + head] = pl;
                g_er1[gm * HEADS + head] = pr;
            }
#pragma unroll
            for (int j = 0; j < 8; j += 4) {
                float4 v = make_float4(acc[i][j], acc[i][j + 1], acc[i][j + 2], acc[i][j + 3]);
                *reinterpret_cast<float4*>(&g_z1[(long)gm * F1 + tx * 8 + j]) = v;
            }
        }
    }
}

// ---------------- layer1: online edge-softmax + aggregate + bias + ELU -----
// one warp per dst node; single pass, 4-edge batches for MLP.
__global__ void agg1_kernel(const int* __restrict__ src, const float* __restrict__ b1) {
    int warp = (blockIdx.x * blockDim.x + threadIdx.x) >> 5;
    int lane = threadIdx.x & 31;
    if (warp >= N_NODES) return;
    int n = warp;
    int s0 = g_row[n], s1 = g_row[n + 1];
    int h = lane >> 3;
    float ern = g_er1[n * HEADS + h];
    int coff = lane * 4;

    float m = -1e30f;
    float denom = 0.f;
    float a0 = 0.f, a1 = 0.f, a2 = 0.f, a3 = 0.f;

    int j = s0;
    for (; j + 4 <= s1; j += 4) {
        // batch-load indices, logits, features (independent -> high MLP)
        int sA = src[j], sB = src[j + 1], sC = src[j + 2], sD = src[j + 3];
        float eA = g_el1[sA * HEADS + h] + ern;
        float eB = g_el1[sB * HEADS + h] + ern;
        float eC = g_el1[sC * HEADS + h] + ern;
        float eD = g_el1[sD * HEADS + h] + ern;
        float4 zA = *reinterpret_cast<const float4*>(&g_z1[(long)sA * F1 + coff]);
        float4 zB = *reinterpret_cast<const float4*>(&g_z1[(long)sB * F1 + coff]);
        float4 zC = *reinterpret_cast<const float4*>(&g_z1[(long)sC * F1 + coff]);
        float4 zD = *reinterpret_cast<const float4*>(&g_z1[(long)sD * F1 + coff]);
        eA = eA > 0.f ? eA : NEG * eA;
        eB = eB > 0.f ? eB : NEG * eB;
        eC = eC > 0.f ? eC : NEG * eC;
        eD = eD > 0.f ? eD : NEG * eD;
        float mn = fmaxf(fmaxf(fmaxf(m, eA), fmaxf(eB, eC)), eD);
        float c  = __expf(m - mn);    // 0 on first batch (m = -1e30)
        float pA = __expf(eA - mn);
        float pB = __expf(eB - mn);
        float pC = __expf(eC - mn);
        float pD = __expf(eD - mn);
        m = mn;
        denom = denom * c + ((pA + pB) + (pC + pD));
        a0 = a0 * c + zA.x * pA + zB.x * pB + zC.x * pC + zD.x * pD;
        a1 = a1 * c + zA.y * pA + zB.y * pB + zC.y * pC + zD.y * pD;
        a2 = a2 * c + zA.z * pA + zB.z * pB + zC.z * pC + zD.z * pD;
        a3 = a3 * c + zA.w * pA + zB.w * pB + zC.w * pC + zD.w * pD;
    }
    for (; j < s1; j++) {
        int s = src[j];
        float e = g_el1[s * HEADS + h] + ern;
        e = e > 0.f ? e : NEG * e;
        float mn = fmaxf(m, e);
        float c = __expf(m - mn);
        float p = __expf(e - mn);
        m = mn;
        denom = denom * c + p;
        float4 z = *reinterpret_cast<const float4*>(&g_z1[(long)s * F1 + coff]);
        a0 = a0 * c + z.x * p;
        a1 = a1 * c + z.y * p;
        a2 = a2 * c + z.z * p;
        a3 = a3 * c + z.w * p;
    }

    float inv = 1.f / fmaxf(denom, 1e-9f);
    float4 bb = *reinterpret_cast<const float4*>(&b1[coff]);
    float o0 = a0 * inv + bb.x;
    float o1 = a1 * inv + bb.y;
    float o2 = a2 * inv + bb.z;
    float o3 = a3 * inv + bb.w;
    // ELU
    o0 = o0 > 0.f ? o0 : expm1f(o0);
    o1 = o1 > 0.f ? o1 : expm1f(o1);
    o2 = o2 > 0.f ? o2 : expm1f(o2);
    o3 = o3 > 0.f ? o3 : expm1f(o3);
    *reinterpret_cast<float4*>(&g_h[(long)n * F1 + coff]) = make_float4(o0, o1, o2, o3);
}

// ---------------- GEMM2 + el2/er2: z2 = h @ W2[128,3] ----------------------
// one warp per node
__global__ void gemm2_kernel(const float* __restrict__ W2, const float* __restrict__ al2,
                             const float* __restrict__ ar2) {
    __shared__ float sW[F1 * OUT_DIM];
    int tid = threadIdx.x;
    for (int i = tid; i < F1 * OUT_DIM; i += blockDim.x) sW[i] = W2[i];
    __syncthreads();
    int warp = (blockIdx.x * blockDim.x + tid) >> 5;
    int lane = tid & 31;
    if (warp >= N_NODES) return;
    float4 hv = *reinterpret_cast<const float4*>(&g_h[(long)warp * F1 + lane * 4]);
    float v[4] = {hv.x, hv.y, hv.z, hv.w};
    float p0 = 0.f, p1 = 0.f, p2 = 0.f;
#pragma unroll
    for (int t = 0; t < 4; t++) {
        int k = lane * 4 + t;
        p0 += v[t] * sW[k * 3 + 0];
        p1 += v[t] * sW[k * 3 + 1];
        p2 += v[t] * sW[k * 3 + 2];
    }
#pragma unroll
    for (int o = 16; o; o >>= 1) {
        p0 += __shfl_xor_sync(0xffffffffu, p0, o);
        p1 += __shfl_xor_sync(0xffffffffu, p1, o);
        p2 += __shfl_xor_sync(0xffffffffu, p2, o);
    }
    if (lane == 0) {
        g_z2[warp * 3 + 0] = p0;
        g_z2[warp * 3 + 1] = p1;
        g_z2[warp * 3 + 2] = p2;
        g_el2[warp] = p0 * al2[0] + p1 * al2[1] + p2 * al2[2];
        g_er2[warp] = p0 * ar2[0] + p1 * ar2[1] + p2 * ar2[2];
    }
}

// ---------------- layer2 edge-softmax + aggregate + bias -> out ------------
__global__ void agg2_kernel(const int* __restrict__ src, const float* __restrict__ b2,
                            float* __restrict__ out) {
    int warp = (blockIdx.x * blockDim.x + threadIdx.x) >> 5;
    int lane = threadIdx.x & 31;
    if (warp >= N_NODES) return;
    int n = warp;
    int s0 = g_row[n], s1 = g_row[n + 1];
    float ern = g_er2[n];
    float m = -1e30f;
    for (int j = s0 + lane; j < s1; j += 32) {
        float e = g_el2[src[j]] + ern;
        e = e > 0.f ? e : NEG * e;
        m = fmaxf(m, e);
    }
#pragma unroll
    for (int o = 16; o; o >>= 1) m = fmaxf(m, __shfl_xor_sync(0xffffffffu, m, o));
    float sd = 0.f, a0 = 0.f, a1 = 0.f, a2 = 0.f;
    for (int j = s0 + lane; j < s1; j += 32) {
        int s = src[j];
        float e = g_el2[s] + ern;
        e = e > 0.f ? e : NEG * e;
        float p = __expf(e - m);
        sd += p;
        a0 += p * g_z2[s * 3 + 0];
        a1 += p * g_z2[s * 3 + 1];
        a2 += p * g_z2[s * 3 + 2];
    }
#pragma unroll
    for (int o = 16; o; o >>= 1) {
        sd += __shfl_xor_sync(0xffffffffu, sd, o);
        a0 += __shfl_xor_sync(0xffffffffu, a0, o);
        a1 += __shfl_xor_sync(0xffffffffu, a1, o);
        a2 += __shfl_xor_sync(0xffffffffu, a2, o);
    }
    if (lane < 3) {
        float inv = 1.f / fmaxf(sd, 1e-9f);
        float acc = (lane == 0) ? a0 : (lane == 1) ? a1 : a2;
        out[n * 3 + lane] = acc * inv + b2[lane];
    }
}

// ---------------- launch ----------------------------------------------------
extern "C" void kernel_launch(void* const* d_in, const int* in_sizes, int n_in,
                              void* d_out, int out_size) {
    const float* features = (const float*)d_in[0];
    const int*   src      = (const int*)d_in[1];
    const int*   dst      = (const int*)d_in[2];
    const float* W1       = (const float*)d_in[3];
    const float* al1      = (const float*)d_in[4];
    const float* ar1      = (const float*)d_in[5];
    const float* b1       = (const float*)d_in[6];
    const float* W2       = (const float*)d_in[7];
    const float* al2      = (const float*)d_in[8];
    const float* ar2      = (const float*)d_in[9];
    const float* b2       = (const float*)d_in[10];
    float* out = (float*)d_out;
    int E = in_sizes[1];

    build_offsets<<<(E + 255) / 256, 256>>>(dst, E);
    gemm1_kernel<<<(N_NODES + 127) / 128, 256>>>(features, W1, al1, ar1);

    int warps_blocks = (N_NODES * 32 + 255) / 256;   // 8 warps/block
    agg1_kernel<<<warps_blocks, 256>>>(src, b1);
    gemm2_kernel<<<warps_blocks, 256>>>(W2, al2, ar2);
    agg2_kernel<<<warps_blocks, 256>>>(src, b2, out);
}